// round 5
// baseline (speedup 1.0000x reference)
#include <cuda_runtime.h>
#include <cuda_bf16.h>

#define PP     76800     // H*W
#define HH     240
#define WW     320
#define NC     22        // classes
#define NG     6         // u64 groups of 4 u16 class lanes (24 >= 22)
#define NGP    7         // padded row stride in u64 (56B -> 2-way max conflicts)
#define NQ     300       // query points (15*20)
#define QW     20        // queries per row
#define QSKIP  16
#define EPSF   1e-6f
#define C1F    (0.9f * 1e-6f)

#define VTHR   640            // k_vote threads (2 copies of 300 queries)
#define VBLKS  HH             // 240 blocks, one image row each
#define RTHR   704            // k_reduce threads (22 warps)
#define RBLKS  240            // k_reduce blocks, 320 px each

// ---------------- device scratch (zero-init; restored to zero every launch) --
__device__ float4             g_pix[PP];        // ux, uy, dz, lab(bits)
__device__ unsigned long long g_accP[NQ * NG];  // votes: 4 u16 class lanes / u64
__device__ int                g_clsCnt[NC];
__device__ float              g_zsum[NC];
__device__ int                g_done;

// ---------------- shared inlier test (identical rounding in vote & reduce) ---
// Equivalent (in reals) to  (cx*ux+cy*uy)/(sqrt(cx^2+cy^2)+eps) > 0.9
__device__ __forceinline__ bool itest(float cx, float cy, float ux, float uy) {
    float rhs = fmaf(cx * cx, 0.81f, (0.81f * cy) * cy);
    float t   = fmaf(cx, ux, fmaf(cy, uy, -C1F));
    return t * fabsf(t) > rhs;
}

// =============== kernel 1: fused per-pixel prep + O(Q*P) vote ================
// 240 blocks (1 row), 640 threads: threads 0..299 = queries scanning px 0..159,
// threads 320..619 = same queries scanning px 160..319. Pixel pairs staged in
// smem; loads batched 2 pairs ahead of the conditional histogram stores so the
// LDS chain pipelines (MLP=4) despite smem-store alias barriers.
__global__ void __launch_bounds__(VTHR, 2) k_vote(const int* __restrict__ label,
                                                  const float* __restrict__ vp) {
    __shared__ float4             sU4[WW / 2];          // (ux0,uy0,ux1,uy1)
    __shared__ unsigned int       sLab2[WW / 2];        // two u16 labels
    __shared__ unsigned long long sCnt[2 * NQ * NGP];   // 33.6 KB

    int t = threadIdx.x;
    #pragma unroll
    for (int i = t; i < 2 * NQ * NGP; i += VTHR) sCnt[i] = 0ULL;

    // --- prep: one pixel per thread (threads 0..319) ---
    int row = blockIdx.x;
    if (t < WW) {
        int p   = row * WW + t;
        int lab = label[p];
        float ux = 0.0f, uy = 0.0f, dz = 0.0f;
        if (lab > 0) {
            float dx = vp[(3 * lab + 0) * PP + p];
            float dy = vp[(3 * lab + 1) * PP + p];
            dz       = vp[(3 * lab + 2) * PP + p];
            float dn = sqrtf(dx * dx + dy * dy) + EPSF;
            ux = dx / dn;
            uy = dy / dn;
        }
        reinterpret_cast<float2*>(sU4)[t]           = make_float2(ux, uy);
        reinterpret_cast<unsigned short*>(sLab2)[t] = (unsigned short)lab;
        g_pix[p] = make_float4(ux, uy, dz, __int_as_float(lab));
    }
    __syncthreads();

    // --- vote: 40 chunks of 2 pixel-pairs (4 px) per thread ---
    int copy = (t >= 320);
    int tq   = t - copy * 320;
    if (tq < NQ) {
        float qx = (float)((tq % QW) * QSKIP);
        float qy = (float)((tq / QW) * QSKIP);
        float cy = qy - (float)row;
        float K  = (0.81f * cy) * cy;                       // loop-invariant
        unsigned short* myC =
            reinterpret_cast<unsigned short*>(&sCnt[(copy * NQ + tq) * NGP]);
        const float4*       su = sU4   + copy * 80;
        const unsigned int* sl = sLab2 + copy * 80;
        float cx0 = qx - (float)(copy * 160);
        #pragma unroll 4
        for (int j = 0; j < 80; j += 2) {
            // batch all loads first (independent, pipeline in LSU)
            float4       ua = su[j];
            float4       ub = su[j + 1];
            unsigned int la = sl[j];
            unsigned int lb = sl[j + 1];
            float cx1 = cx0 - 1.0f;
            float cx2 = cx0 - 2.0f;
            float cx3 = cx0 - 3.0f;
            float r0 = fmaf(cx0 * cx0, 0.81f, K);
            float t0 = fmaf(cx0, ua.x, fmaf(cy, ua.y, -C1F));
            float r1 = fmaf(cx1 * cx1, 0.81f, K);
            float t1 = fmaf(cx1, ua.z, fmaf(cy, ua.w, -C1F));
            float r2 = fmaf(cx2 * cx2, 0.81f, K);
            float t2 = fmaf(cx2, ub.x, fmaf(cy, ub.y, -C1F));
            float r3 = fmaf(cx3 * cx3, 0.81f, K);
            float t3 = fmaf(cx3, ub.z, fmaf(cy, ub.w, -C1F));
            if (t0 * fabsf(t0) > r0) myC[la & 0xFFFFu] += 1;
            if (t1 * fabsf(t1) > r1) myC[la >> 16]     += 1;
            if (t2 * fabsf(t2) > r2) myC[lb & 0xFFFFu] += 1;
            if (t3 * fabsf(t3) > r3) myC[lb >> 16]     += 1;
            cx0 -= 4.0f;                                    // exact small ints
        }
    }
    __syncthreads();

    // --- flush: merge copies (u64 lane add, no carry: lanes <= 320) + RED ---
    if (t < NQ) {
        #pragma unroll
        for (int g = 0; g < NG; g++) {
            unsigned long long v = sCnt[t * NGP + g] + sCnt[(NQ + t) * NGP + g];
            if (v) atomicAdd(&g_accP[t * NG + g], v);       // exact u16 lanes
        }
    }
}

// =============== kernel 2: fused argmax + z-sum + final + cleanup ============
__global__ void __launch_bounds__(RTHR) k_reduce(const float* __restrict__ extents,
                                                 const float* __restrict__ poses,
                                                 const float* __restrict__ mdata,
                                                 float* __restrict__ out) {
    __shared__ unsigned long long sT[NQ * NG];   // 14.4 KB raw vote table
    __shared__ int   sBQ[NC];
    __shared__ float sBV[NC];
    __shared__ float sZ[NC];
    __shared__ int   sCC[NC];
    __shared__ int   sLast;

    int t    = threadIdx.x;
    int lane = t & 31;
    int w    = t >> 5;

    // issue the pixel load FIRST: its latency hides under staging + argmax
    float4 pv = make_float4(0.f, 0.f, 0.f, 0.f);
    if (t < WW) pv = g_pix[blockIdx.x * WW + t];

    if (t < NC) { sZ[t] = 0.0f; sCC[t] = 0; }
    if (t == 0) sLast = 0;

    // --- stage raw u64 vote table (coalesced; L2-broadcast across blocks) ---
    for (int i = t; i < NQ * NG; i += RTHR) sT[i] = g_accP[i];
    __syncthreads();

    // --- per-class argmax on u16 lanes, integer compare (first-index ties) ---
    if (w < NC) {
        int g  = w >> 2;
        int sh = (w & 3) * 16;
        int best = -1, bq = 0;
        for (int q = lane; q < NQ; q += 32) {
            int v = (int)((sT[q * NG + g] >> sh) & 0xFFFFu);
            if (v > best) { best = v; bq = q; }
        }
        #pragma unroll
        for (int off = 16; off; off >>= 1) {
            int ov = __shfl_down_sync(0xffffffffu, best, off);
            int oq = __shfl_down_sync(0xffffffffu, bq,   off);
            if (ov > best || (ov == best && oq < bq)) { best = ov; bq = oq; }
        }
        if (lane == 0) { sBQ[w] = bq; sBV[w] = (float)best; }
    }
    __syncthreads();

    // --- z-sum + class counts over this block's 320 pixels ---
    if (t < WW) {                                      // warps 0..9 fully active
        int lab = __float_as_int(pv.w);
        unsigned m = __match_any_sync(0xffffffffu, lab);
        if (lane == __ffs(m) - 1) atomicAdd(&sCC[lab], __popc(m));
        if (lab > 0) {
            int q = sBQ[lab];
            float qx = (float)((q % QW) * QSKIP);
            float qy = (float)((q / QW) * QSKIP);
            float cx = qx - (float)t;                  // t == column in this row
            float cy = qy - (float)blockIdx.x;
            if (itest(cx, cy, pv.x, pv.y))             // same rounding as k_vote
                atomicAdd(&sZ[lab], pv.z);
        }
    }
    __syncthreads();

    if (t < NC) {
        if (sCC[t])        atomicAdd(&g_clsCnt[t], sCC[t]);
        if (sZ[t] != 0.0f) atomicAdd(&g_zsum[t], sZ[t]);
    }
    __threadfence();
    __syncthreads();
    if (t == 0) {
        int ticket = atomicAdd(&g_done, 1);
        if (ticket == RBLKS - 1) sLast = 1;
    }
    __syncthreads();
    if (!sLast) return;

    // ================= last block: assemble output + reset scratch ===========
    if (t < NC) {
        __threadfence();     // acquire published g_zsum / g_clsCnt
        int c = t;
        float fx  = mdata[0] + EPSF;
        float fy  = mdata[4] + EPSF;
        float ppx = mdata[2];
        float ppy = mdata[5];

        float bv = sBV[c];
        int   bq = sBQ[c];
        float bx = (float)((bq % QW) * QSKIP);
        float by = (float)((bq / QW) * QSKIP);

        float cc = (float)g_clsCnt[c];
        float z  = g_zsum[c] / (bv + EPSF);   // cnt == best_votes (identity)

        float ex = extents[c * 3 + 0];
        float ey = extents[c * 3 + 1];
        float ez = extents[c * 3 + 2];
        float half = 0.5f * sqrtf(ex * ex + ey * ey + ez * ez);

        float zsafe = (fabsf(z) > EPSF) ? z : EPSF;
        float r = fx * half / zsafe;

        bool valid = (bv >= 50.0f) && (cc >= 500.0f) && (bv / (cc + EPSF) >= 0.02f);
        float score = valid ? bv : 0.0f;

        float* o = out + c * 14;
        o[0]  = 0.0f;
        o[1]  = (float)c;
        o[2]  = bx - r;
        o[3]  = by - r;
        o[4]  = bx + r;
        o[5]  = by + r;
        o[6]  = score;
        o[7]  = poses[c * 13 + 6];
        o[8]  = poses[c * 13 + 7];
        o[9]  = poses[c * 13 + 8];
        o[10] = poses[c * 13 + 9];
        o[11] = (bx - ppx) * z / fx;
        o[12] = (by - ppy) * z / fy;
        o[13] = z;

        // reset per-launch accumulators for the next graph replay
        g_clsCnt[c] = 0;
        g_zsum[c]   = 0.0f;
    }
    for (int i = t; i < NQ * NG; i += RTHR) g_accP[i] = 0ULL;
    if (t == 0) g_done = 0;
}

// ---------------- launch ------------------------------------------------------
extern "C" void kernel_launch(void* const* d_in, const int* in_sizes, int n_in,
                              void* d_out, int out_size) {
    const int*   label   = (const int*)  d_in[0];   // (1,240,320) int32
    const float* vp      = (const float*)d_in[1];   // (1,66,240,320) f32
    const float* extents = (const float*)d_in[2];   // (22,3) f32
    const float* poses   = (const float*)d_in[3];   // (22,13) f32
    const float* mdata   = (const float*)d_in[4];   // (1,9) f32
    float*       out     = (float*)d_out;           // (1,22,14) f32

    k_vote  <<<VBLKS, VTHR>>>(label, vp);
    k_reduce<<<RBLKS, RTHR>>>(extents, poses, mdata, out);
}

// round 6
// speedup vs baseline: 1.3825x; 1.3825x over previous
#include <cuda_runtime.h>
#include <cuda_bf16.h>

#define PP     76800     // H*W
#define HH     240
#define WW     320
#define NC     22        // classes
#define NG     6         // u64 groups of 4 u16 class lanes (24 >= 22)
#define RPAD   36        // u8 histogram row stride (9 words, gcd(9,32)=1)
#define NQ     300       // query points (15*20)
#define QW     20        // queries per row
#define QSKIP  16
#define EPSF   1e-6f
#define C1F    (0.9f * 1e-6f)

#define VTHR   640            // k_vote threads (2 copies of 300 queries)
#define VBLKS  HH             // 240 blocks, one image row each
#define RTHR   704            // k_reduce threads (22 warps)
#define RBLKS  120            // k_reduce blocks, 640 px (2 rows) each

// ---------------- device scratch (zero-init; restored to zero every launch) --
__device__ float4             g_pix[PP];        // ux, uy, dz, lab(bits)
__device__ unsigned long long g_accP[NQ * NG];  // votes: 4 u16 class lanes / u64
__device__ int                g_clsCnt[NC];
__device__ float              g_zsum[NC];
__device__ int                g_done;

// ---------------- shared inlier test (identical rounding in vote & reduce) ---
// Equivalent (in reals) to  (cx*ux+cy*uy)/(sqrt(cx^2+cy^2)+eps) > 0.9
__device__ __forceinline__ bool itest(float cx, float cy, float ux, float uy) {
    float rhs = fmaf(cx * cx, 0.81f, (0.81f * cy) * cy);
    float t   = fmaf(cx, ux, fmaf(cy, uy, -C1F));
    return t * fabsf(t) > rhs;
}

// =============== kernel 1: fused per-pixel prep + O(Q*P) vote ================
// 240 blocks (1 row), 640 threads: threads 0..299 = queries scanning px 0..159,
// threads 320..619 = same queries scanning px 160..319. Pixel pairs staged in
// smem; private u8 histogram rows (counts <= 160) -> no atomics in hot loop.
// ~25 KB smem / moderate regs => 2 blocks per SM co-reside for latency hiding.
__global__ void __launch_bounds__(VTHR) k_vote(const int* __restrict__ label,
                                               const float* __restrict__ vp) {
    __shared__ float4        sU4[WW / 2];           // (ux0,uy0,ux1,uy1)
    __shared__ unsigned int  sLab2[WW / 2];         // two u16 labels
    __shared__ unsigned char sCnt[2 * NQ * RPAD];   // 21.6 KB, u8 lanes

    int t = threadIdx.x;
    #pragma unroll
    for (int i = t; i < 2 * NQ * RPAD / 4; i += VTHR)
        reinterpret_cast<unsigned int*>(sCnt)[i] = 0u;

    // --- prep: one pixel per thread (threads 0..319) ---
    int row = blockIdx.x;
    if (t < WW) {
        int p   = row * WW + t;
        int lab = label[p];
        float ux = 0.0f, uy = 0.0f, dz = 0.0f;
        if (lab > 0) {
            float dx = vp[(3 * lab + 0) * PP + p];
            float dy = vp[(3 * lab + 1) * PP + p];
            dz       = vp[(3 * lab + 2) * PP + p];
            float dn = sqrtf(dx * dx + dy * dy) + EPSF;
            ux = dx / dn;
            uy = dy / dn;
        }
        reinterpret_cast<float2*>(sU4)[t]           = make_float2(ux, uy);
        reinterpret_cast<unsigned short*>(sLab2)[t] = (unsigned short)lab;
        g_pix[p] = make_float4(ux, uy, dz, __int_as_float(lab));
    }
    __syncthreads();

    // --- vote: 80 pixel-pairs per thread (R4-style slim body) ---
    int copy = (t >= 320);
    int tq   = t - copy * 320;
    if (tq < NQ) {
        float qx = (float)((tq % QW) * QSKIP);
        float qy = (float)((tq / QW) * QSKIP);
        float cy = qy - (float)row;
        float K  = (0.81f * cy) * cy;                       // loop-invariant
        unsigned char* myC = &sCnt[(copy * NQ + tq) * RPAD];
        const float4*       su = sU4   + copy * 80;
        const unsigned int* sl = sLab2 + copy * 80;
        float cx0 = qx - (float)(copy * 160);
        #pragma unroll 8
        for (int j = 0; j < 80; j++) {
            float4       u    = su[j];                      // smem broadcast
            unsigned int lab2 = sl[j];                      // smem broadcast
            float rhs0 = fmaf(cx0 * cx0, 0.81f, K);
            float t0   = fmaf(cx0, u.x, fmaf(cy, u.y, -C1F));
            if (t0 * fabsf(t0) > rhs0) myC[lab2 & 0xFFFFu] += 1;
            float cx1  = cx0 - 1.0f;
            float rhs1 = fmaf(cx1 * cx1, 0.81f, K);
            float t1   = fmaf(cx1, u.z, fmaf(cy, u.w, -C1F));
            if (t1 * fabsf(t1) > rhs1) myC[lab2 >> 16] += 1;
            cx0 -= 2.0f;                                    // exact small ints
        }
    }
    __syncthreads();

    // --- flush: widen u8->u16 lanes, merge copies, 6 u64 REDs per query ---
    if (t < NQ) {
        const unsigned int* ra =
            reinterpret_cast<const unsigned int*>(&sCnt[t * RPAD]);
        const unsigned int* rb =
            reinterpret_cast<const unsigned int*>(&sCnt[(NQ + t) * RPAD]);
        #pragma unroll
        for (int g = 0; g < NG; g++) {
            unsigned int va = ra[g], vb = rb[g];
            unsigned int lo = __byte_perm(va, 0, 0x4140)
                            + __byte_perm(vb, 0, 0x4140);   // b0|b1<<16 lanes
            unsigned int hi = __byte_perm(va, 0, 0x4342)
                            + __byte_perm(vb, 0, 0x4342);   // b2|b3<<16 lanes
            unsigned long long v = (unsigned long long)lo
                                 | ((unsigned long long)hi << 32);
            if (v) atomicAdd(&g_accP[t * NG + g], v);       // exact u16 lanes
        }
    }
}

// =============== kernel 2: fused argmax + z-sum + final + cleanup ============
// 120 blocks (single wave), 640 px each.
__global__ void __launch_bounds__(RTHR) k_reduce(const float* __restrict__ extents,
                                                 const float* __restrict__ poses,
                                                 const float* __restrict__ mdata,
                                                 float* __restrict__ out) {
    __shared__ unsigned long long sT[NQ * NG];   // 14.4 KB raw vote table
    __shared__ int   sBQ[NC];
    __shared__ float sBV[NC];
    __shared__ float sZ[NC];
    __shared__ int   sCC[NC];
    __shared__ int   sLast;

    int t    = threadIdx.x;
    int lane = t & 31;
    int w    = t >> 5;

    // issue the pixel load FIRST: its latency hides under staging + argmax
    float4 pv = make_float4(0.f, 0.f, 0.f, 0.f);
    if (t < 2 * WW) pv = g_pix[blockIdx.x * (2 * WW) + t];

    if (t < NC) { sZ[t] = 0.0f; sCC[t] = 0; }
    if (t == 0) sLast = 0;

    // --- stage raw u64 vote table (coalesced; L2-broadcast across blocks) ---
    for (int i = t; i < NQ * NG; i += RTHR) sT[i] = g_accP[i];
    __syncthreads();

    // --- per-class argmax on u16 lanes, integer compare (first-index ties) ---
    if (w < NC) {
        int g  = w >> 2;
        int sh = (w & 3) * 16;
        int best = -1, bq = 0;
        for (int q = lane; q < NQ; q += 32) {
            int v = (int)((sT[q * NG + g] >> sh) & 0xFFFFu);
            if (v > best) { best = v; bq = q; }
        }
        #pragma unroll
        for (int off = 16; off; off >>= 1) {
            int ov = __shfl_down_sync(0xffffffffu, best, off);
            int oq = __shfl_down_sync(0xffffffffu, bq,   off);
            if (ov > best || (ov == best && oq < bq)) { best = ov; bq = oq; }
        }
        if (lane == 0) { sBQ[w] = bq; sBV[w] = (float)best; }
    }
    __syncthreads();

    // --- z-sum + class counts over this block's 640 pixels (2 rows) ---
    if (t < 2 * WW) {                                  // warps 0..19 fully active
        int lab = __float_as_int(pv.w);
        unsigned m = __match_any_sync(0xffffffffu, lab);
        if (lane == __ffs(m) - 1) atomicAdd(&sCC[lab], __popc(m));
        if (lab > 0) {
            int q = sBQ[lab];
            int sub = (t >= WW);                       // row within block
            int col = t - sub * WW;
            float qx = (float)((q % QW) * QSKIP);
            float qy = (float)((q / QW) * QSKIP);
            float cx = qx - (float)col;
            float cy = qy - (float)(blockIdx.x * 2 + sub);
            if (itest(cx, cy, pv.x, pv.y))             // same rounding as k_vote
                atomicAdd(&sZ[lab], pv.z);
        }
    }
    __syncthreads();

    if (t < NC) {
        if (sCC[t])        atomicAdd(&g_clsCnt[t], sCC[t]);
        if (sZ[t] != 0.0f) atomicAdd(&g_zsum[t], sZ[t]);
    }
    __threadfence();
    __syncthreads();
    if (t == 0) {
        int ticket = atomicAdd(&g_done, 1);
        if (ticket == RBLKS - 1) sLast = 1;
    }
    __syncthreads();
    if (!sLast) return;

    // ================= last block: assemble output + reset scratch ===========
    if (t < NC) {
        __threadfence();     // acquire published g_zsum / g_clsCnt
        int c = t;
        float fx  = mdata[0] + EPSF;
        float fy  = mdata[4] + EPSF;
        float ppx = mdata[2];
        float ppy = mdata[5];

        float bv = sBV[c];
        int   bq = sBQ[c];
        float bx = (float)((bq % QW) * QSKIP);
        float by = (float)((bq / QW) * QSKIP);

        float cc = (float)g_clsCnt[c];
        float z  = g_zsum[c] / (bv + EPSF);   // cnt == best_votes (identity)

        float ex = extents[c * 3 + 0];
        float ey = extents[c * 3 + 1];
        float ez = extents[c * 3 + 2];
        float half = 0.5f * sqrtf(ex * ex + ey * ey + ez * ez);

        float zsafe = (fabsf(z) > EPSF) ? z : EPSF;
        float r = fx * half / zsafe;

        bool valid = (bv >= 50.0f) && (cc >= 500.0f) && (bv / (cc + EPSF) >= 0.02f);
        float score = valid ? bv : 0.0f;

        float* o = out + c * 14;
        o[0]  = 0.0f;
        o[1]  = (float)c;
        o[2]  = bx - r;
        o[3]  = by - r;
        o[4]  = bx + r;
        o[5]  = by + r;
        o[6]  = score;
        o[7]  = poses[c * 13 + 6];
        o[8]  = poses[c * 13 + 7];
        o[9]  = poses[c * 13 + 8];
        o[10] = poses[c * 13 + 9];
        o[11] = (bx - ppx) * z / fx;
        o[12] = (by - ppy) * z / fy;
        o[13] = z;

        // reset per-launch accumulators for the next graph replay
        g_clsCnt[c] = 0;
        g_zsum[c]   = 0.0f;
    }
    for (int i = t; i < NQ * NG; i += RTHR) g_accP[i] = 0ULL;
    if (t == 0) g_done = 0;
}

// ---------------- launch ------------------------------------------------------
extern "C" void kernel_launch(void* const* d_in, const int* in_sizes, int n_in,
                              void* d_out, int out_size) {
    const int*   label   = (const int*)  d_in[0];   // (1,240,320) int32
    const float* vp      = (const float*)d_in[1];   // (1,66,240,320) f32
    const float* extents = (const float*)d_in[2];   // (22,3) f32
    const float* poses   = (const float*)d_in[3];   // (22,13) f32
    const float* mdata   = (const float*)d_in[4];   // (1,9) f32
    float*       out     = (float*)d_out;           // (1,22,14) f32

    k_vote  <<<VBLKS, VTHR>>>(label, vp);
    k_reduce<<<RBLKS, RTHR>>>(extents, poses, mdata, out);
}